// round 1
// baseline (speedup 1.0000x reference)
#include <cuda_runtime.h>
#include <cuda_bf16.h>

// BrockHommes sequential scan, lag-4 dependence => 4-way parallel groups.
// One warp; lanes 0..3 each compute one timestep of the current group of 4,
// including a private 4-wide softmax in registers. Window state (x_{t-4},
// x_{t-5}, x_{t-6}) is exchanged via __shfl_sync after each group.

#define BH_MASK 0x0000000Fu

__global__ void __launch_bounds__(32, 1) bh_scan_kernel(
    const float* __restrict__ params,
    const float* __restrict__ eps,
    float* __restrict__ out,
    int n)
{
    const int lane = (int)threadIdx.x;
    if (lane >= 4) return;

    // --- derived parameters (uniform across lanes) ---
    const float beta  = expf(params[0]);
    const float sigma = expf(params[9]);     // params[-2]
    const float R     = 1.0f + expf(params[10]); // params[-1]
    // fold 1/ln(2) into beta so the softmax uses exp2f (EX2 path)
    const float beta2 = beta * 1.44269504088896340736f;

    const float g0 = params[1], g1 = params[2], g2 = params[3], g3 = params[4];
    const float b0 = params[5], b1 = params[6], b2 = params[7], b3 = params[8];

    // per-lane window state for timestep t = 4*grp + lane:
    // p4 = x_{t-4}, p5 = x_{t-5}, p6 = x_{t-6}; init carry is zeros.
    float p4 = 0.0f, p5 = 0.0f, p6 = 0.0f;

    const int ngroups = n >> 2;
    int t = lane;
    float e_next = (t < n) ? eps[t] : 0.0f;   // prefetched epsilon

    for (int grp = 0; grp < ngroups; ++grp, t += 4) {
        const float es = e_next * sigma;
        if (t + 4 < n) e_next = eps[t + 4];   // prefetch next group's epsilon

        // exponent_i = beta * (xm4 - R*xm5) * (g_i*xm6 + b_i - R*xm5)
        const float rx5 = R * p5;
        const float a   = beta2 * (p4 - rx5);        // includes 1/ln2
        const float c0  = fmaf(g0, p6, b0 - rx5);
        const float c1  = fmaf(g1, p6, b1 - rx5);
        const float c2  = fmaf(g2, p6, b2 - rx5);
        const float c3  = fmaf(g3, p6, b3 - rx5);
        const float e0 = a * c0, e1 = a * c1, e2 = a * c2, e3 = a * c3;

        // stabilized softmax (max-subtraction, like jax.nn.softmax)
        const float m  = fmaxf(fmaxf(e0, e1), fmaxf(e2, e3));
        const float q0 = exp2f(e0 - m);
        const float q1 = exp2f(e1 - m);
        const float q2 = exp2f(e2 - m);
        const float q3 = exp2f(e3 - m);

        // y_i = g_i*xm4 + b_i
        const float y0 = fmaf(g0, p4, b0);
        const float y1 = fmaf(g1, p4, b1);
        const float y2 = fmaf(g2, p4, b2);
        const float y3 = fmaf(g3, p4, b3);

        const float S0 = (q0 + q1) + (q2 + q3);
        const float S1 = fmaf(q0, y0, q1 * y1) + fmaf(q2, y2, q3 * y3);

        // x = (S1/S0 + es) / R  ==  (S1 + es*S0) / (S0*R)   (single division)
        const float x = fmaf(es, S0, S1) / (S0 * R);

        out[t] = x;

        // --- window update via shuffles ---
        // next step t' = t+4 needs: x_{t'-4}=x_t (own), x_{t'-5}=x_{t-1},
        // x_{t'-6}=x_{t-2}. For low lanes these come from the PREVIOUS
        // group's lane-3/lane-2 p4 (which equal x_{4g-1}, x_{4g-2}).
        const float p4old = p4;
        const float xm1 = __shfl_sync(BH_MASK, x, (lane + 3) & 3); // lane-1's x
        const float xm2 = __shfl_sync(BH_MASK, x, (lane + 2) & 3); // lane-2's x
        const float o3  = __shfl_sync(BH_MASK, p4old, 3);          // x_{4g-1}
        const float o2  = __shfl_sync(BH_MASK, p4old, 2);          // x_{4g-2}

        p6 = (lane >= 2) ? xm2 : ((lane == 1) ? o3 : o2);
        p5 = (lane >= 1) ? xm1 : o3;
        p4 = x;
    }

    // tail (n % 4 leftover steps) — all independent of each other (lag >= 4)
    const int rem = n & 3;
    if (lane < rem) {
        const int tt = 4 * ngroups + lane;
        const float es = eps[tt] * sigma;

        const float rx5 = R * p5;
        const float a   = beta2 * (p4 - rx5);
        const float c0  = fmaf(g0, p6, b0 - rx5);
        const float c1  = fmaf(g1, p6, b1 - rx5);
        const float c2  = fmaf(g2, p6, b2 - rx5);
        const float c3  = fmaf(g3, p6, b3 - rx5);
        const float e0 = a * c0, e1 = a * c1, e2 = a * c2, e3 = a * c3;
        const float m  = fmaxf(fmaxf(e0, e1), fmaxf(e2, e3));
        const float q0 = exp2f(e0 - m);
        const float q1 = exp2f(e1 - m);
        const float q2 = exp2f(e2 - m);
        const float q3 = exp2f(e3 - m);
        const float y0 = fmaf(g0, p4, b0);
        const float y1 = fmaf(g1, p4, b1);
        const float y2 = fmaf(g2, p4, b2);
        const float y3 = fmaf(g3, p4, b3);
        const float S0 = (q0 + q1) + (q2 + q3);
        const float S1 = fmaf(q0, y0, q1 * y1) + fmaf(q2, y2, q3 * y3);
        out[tt] = fmaf(es, S0, S1) / (S0 * R);
    }
}

extern "C" void kernel_launch(void* const* d_in, const int* in_sizes, int n_in,
                              void* d_out, int out_size)
{
    const float* params = (const float*)d_in[0];
    const float* eps    = (const float*)d_in[1];
    float* out          = (float*)d_out;
    const int n = in_sizes[1];

    bh_scan_kernel<<<1, 32>>>(params, eps, out, n);
}